// round 6
// baseline (speedup 1.0000x reference)
#include <cuda_runtime.h>
#include <cstdint>

// CondFilterT: per row b (BATCH=16384):
//   e = table[inp[b,0]]  (64 fp32)   -> out[b, 0:64] raw
//   for c in 0..49: v = table[inp[b,1+c]]
//     filtered = v * dot(e,v) / (||e|| * ||v||^2)  -> out[b, 64+64c : 64+64(c+1)]
//
// R5: float4/lane, 2 rows per warp (one per half-warp).
//  - __launch_bounds__(128,10): force 48 regs -> 62.5% occupancy cap (was 63r/40.5%)
//  - paired butterfly reduction: 5 shfl per condition instead of 8
//  - grid 2048 x 128 threads: smooth wave tail
//  - __fdividef (rel_err budget 1e-3; we're at 2e-8)

#define CF_BATCH  16384
#define CF_NCONDS 50
#define CF_EMB    64
#define CF_ROWLEN (CF_EMB * (1 + CF_NCONDS))   // 3264 floats per output row

__global__ __launch_bounds__(128, 10)
void condfilter_kernel(const int* __restrict__ inp,
                       const float* __restrict__ table,
                       float* __restrict__ out)
{
    const unsigned FULL = 0xFFFFFFFFu;
    const int lane   = threadIdx.x & 31;
    const int half   = lane >> 4;          // row within the warp's pair
    const int hl     = lane & 15;          // lane within half-warp
    const bool lowg  = (hl < 8);           // role for the paired reduction
    const int gwarp  = (blockIdx.x * blockDim.x + threadIdx.x) >> 5;
    const int rowid  = gwarp * 2 + half;   // exact: grid covers CF_BATCH rows

    // ---- 51 indices for this row: index j in reg (j/16) of lane (j%16) ----
    const int* irow = inp + (size_t)rowid * (1 + CF_NCONDS);
    const int idx_a = irow[hl];                         // j = 0..15
    const int idx_b = irow[16 + hl];                    // j = 16..31
    const int idx_c = irow[32 + hl];                    // j = 32..47
    const int idx_d = (hl < 3) ? irow[48 + hl] : 0;     // j = 48..50

    const int hbase = half << 4;   // shfl source-lane base for this half-warp
    const float4* __restrict__ tab4 = (const float4*)table;

    // ---- event embedding + inverse norm (reduce over 16 lanes) ----
    const int e_idx = __shfl_sync(FULL, idx_a, hbase);  // j = 0
    const float4 e = __ldg(tab4 + (size_t)e_idx * (CF_EMB / 4) + hl);
    float ss = e.x * e.x + e.y * e.y + e.z * e.z + e.w * e.w;
    #pragma unroll
    for (int o = 8; o > 0; o >>= 1) ss += __shfl_xor_sync(FULL, ss, o);
    const float e_inv = rsqrtf(ss);

    float4* orow = (float4*)(out + (size_t)rowid * CF_ROWLEN);
    __stcs(orow + hl, e);   // raw event embedding, 256B coalesced, evict-first

    // ---- conditions, 5 at a time ----
    #pragma unroll 2
    for (int c0 = 0; c0 < CF_NCONDS; c0 += 5) {
        float4 cv[5];
        #pragma unroll
        for (int u = 0; u < 5; u++) {
            const int j = 1 + c0 + u;                        // uniform across warp
            const int v = (j < 16) ? idx_a
                        : (j < 32) ? idx_b
                        : (j < 48) ? idx_c : idx_d;           // uniform selects
            const int cidx = __shfl_sync(FULL, v, hbase + (j & 15));
            cv[u] = __ldg(tab4 + (size_t)cidx * (CF_EMB / 4) + hl);
        }

        // paired reduction: lanes hl<8 accumulate ||v||^2, hl>=8 accumulate e.v
        float r[5];
        #pragma unroll
        for (int u = 0; u < 5; u++) {
            const float s1 = cv[u].x * cv[u].x + cv[u].y * cv[u].y
                           + cv[u].z * cv[u].z + cv[u].w * cv[u].w;   // ||v||^2
            const float s2 = e.x * cv[u].x + e.y * cv[u].y
                           + e.z * cv[u].z + e.w * cv[u].w;           // dot(e,v)
            const float give = lowg ? s2 : s1;
            r[u] = (lowg ? s1 : s2) + __shfl_xor_sync(FULL, give, 8);
        }
        #pragma unroll
        for (int o = 4; o > 0; o >>= 1) {
            #pragma unroll
            for (int u = 0; u < 5; u++)
                r[u] += __shfl_xor_sync(FULL, r[u], o);
        }

        #pragma unroll
        for (int u = 0; u < 5; u++) {
            const float other = __shfl_xor_sync(FULL, r[u], 8);
            const float S1 = lowg ? r[u] : other;     // ||v||^2
            const float S2 = lowg ? other : r[u];     // dot(e,v)
            const float sc = __fdividef(S2 * e_inv, S1);
            float4 w;
            w.x = cv[u].x * sc;
            w.y = cv[u].y * sc;
            w.z = cv[u].z * sc;
            w.w = cv[u].w * sc;
            __stcs(orow + 16 + (size_t)(c0 + u) * 16 + hl, w);  // 256B coalesced
        }
    }
}

extern "C" void kernel_launch(void* const* d_in, const int* in_sizes, int n_in,
                              void* d_out, int out_size)
{
    const int*   inp   = (const int*)d_in[0];     // (16384, 51) int32
    const float* table = (const float*)d_in[1];   // (100002, 64) float32
    float*       out   = (float*)d_out;           // (16384, 3264) float32

    // 4 warps/block, 2 rows/warp -> 8 rows per 128-thread block
    const int rows_per_block = (128 / 32) * 2;
    const int grid = CF_BATCH / rows_per_block;   // 2048 (exact)
    condfilter_kernel<<<grid, 128>>>(inp, table, out);
}